// round 4
// baseline (speedup 1.0000x reference)
#include <cuda_runtime.h>

#define BB 32
#define NN 16384
#define DD 64

// ---------------- pass 1 (ctx = softmax(k)^T @ v) ----------------
#define P1_CHUNKS 16
#define P1_CROWS (NN / P1_CHUNKS)    // 1024 rows per block
#define P1_TROWS 32                  // rows per smem tile
#define P1_NT (P1_CROWS / P1_TROWS)  // 32 tiles
#define KST 68                       // padded tile row stride (floats, 16B-mult)
#define SST 68                       // stage row stride

// ---------------- pass 2 (out = softmax(q) @ ctx) ----------------
#define P2_CHUNKS 16
#define P2_CROWS (NN / P2_CHUNKS)    // 1024 rows per block
#define P2_TROWS 64                  // rows per tile
#define P2_NT (P2_CROWS / P2_TROWS)  // 16 tiles
#define QST 68                       // qt row stride (floats)

__device__ float g_ctx[BB * DD * DD];   // 512 KB scratch

// packed fp32x2 FMA (2x fp32 throughput vs scalar FFMA on sm_103a)
__device__ __forceinline__ float2 ffma2(float2 a, float2 b, float2 c) {
    union U { float2 f; unsigned long long u; };
    U A, B2, C, R;
    A.f = a; B2.f = b; C.f = c;
    asm("fma.rn.f32x2 %0, %1, %2, %3;"
        : "=l"(R.u) : "l"(A.u), "l"(B2.u), "l"(C.u));
    return R.f;
}

// softmax over 8 local values replicated across an 8-lane group (lanes share row)
__device__ __forceinline__ void softmax8(float4 a, float4 b, float* o) {
    float m = fmaxf(fmaxf(fmaxf(a.x, a.y), fmaxf(a.z, a.w)),
                    fmaxf(fmaxf(b.x, b.y), fmaxf(b.z, b.w)));
    m = fmaxf(m, __shfl_xor_sync(0xffffffffu, m, 1));
    m = fmaxf(m, __shfl_xor_sync(0xffffffffu, m, 2));
    m = fmaxf(m, __shfl_xor_sync(0xffffffffu, m, 4));
    o[0] = __expf(a.x - m); o[1] = __expf(a.y - m);
    o[2] = __expf(a.z - m); o[3] = __expf(a.w - m);
    o[4] = __expf(b.x - m); o[5] = __expf(b.y - m);
    o[6] = __expf(b.z - m); o[7] = __expf(b.w - m);
    float s = o[0] + o[1] + o[2] + o[3] + o[4] + o[5] + o[6] + o[7];
    s += __shfl_xor_sync(0xffffffffu, s, 1);
    s += __shfl_xor_sync(0xffffffffu, s, 2);
    s += __shfl_xor_sync(0xffffffffu, s, 4);
    float inv = __frcp_rn(s);
#pragma unroll
    for (int i = 0; i < 8; i++) o[i] *= inv;
}

__global__ void zero_ctx_kernel() {
    int i = blockIdx.x * blockDim.x + threadIdx.x;
    if (i < BB * DD * DD) g_ctx[i] = 0.f;
}

// ============================ PASS 1 ============================
// grid (P1_CHUNKS, BB), 256 threads. Each warp owns the full 64x64 ctx
// as an 8x16 per-lane register tile, over its subset of rows.
__global__ void __launch_bounds__(256, 1) ctx_kernel(
    const float* __restrict__ K, const float* __restrict__ V)
{
    extern __shared__ float sm[];
    float* kn    = sm;                         // [P1_TROWS][KST]  softmaxed k
    float* vv    = sm + P1_TROWS * KST;        // [P1_TROWS][KST]  raw v
    float* stage = vv + P1_TROWS * KST;        // [8][DD][SST]     warp partials

    const int b  = blockIdx.y;
    const int n0 = blockIdx.x * P1_CROWS;

    const int tid  = threadIdx.x;
    const int wid  = tid >> 5;
    const int lane = tid & 31;

    // load/softmax mapping: 8 lanes per row, 4 rows per warp
    const int lrow = lane >> 3;          // 0..3
    const int lcol = (lane & 7) << 3;    // 0,8,...,56

    // accumulate mapping: lane -> (d-octet, e-16-group)
    const int ti = lane >> 2;            // 0..7  -> d = 8*ti ..
    const int tj = lane & 3;             // 0..3  -> e = 16*tj ..

    const float* Kb = K + ((size_t)b * NN) * DD;
    const float* Vb = V + ((size_t)b * NN) * DD;

    float2 acc[8][8];
#pragma unroll
    for (int i = 0; i < 8; i++)
#pragma unroll
        for (int j = 0; j < 8; j++) acc[i][j] = make_float2(0.f, 0.f);

    // prefetch tile 0
    const float* kp = Kb + (size_t)(n0 + (wid << 2) + lrow) * DD + lcol;
    const float* vp = Vb + (size_t)(n0 + (wid << 2) + lrow) * DD + lcol;
    float4 k0 = *(const float4*)kp;
    float4 k1 = *(const float4*)(kp + 4);
    float4 v0 = *(const float4*)vp;
    float4 v1 = *(const float4*)(vp + 4);

    for (int it = 0; it < P1_NT; ++it) {
        // softmax k segment in registers, store tile to smem
        float o[8];
        softmax8(k0, k1, o);
        const int srow = (wid << 2) + lrow;
        float* kd = kn + srow * KST + lcol;
        ((float4*)kd)[0] = make_float4(o[0], o[1], o[2], o[3]);
        ((float4*)kd)[1] = make_float4(o[4], o[5], o[6], o[7]);
        float* vd = vv + srow * KST + lcol;
        ((float4*)vd)[0] = v0;
        ((float4*)vd)[1] = v1;
        __syncthreads();

        // prefetch next tile (overlaps FMA phase below)
        if (it + 1 < P1_NT) {
            const float* kp2 = Kb + (size_t)(n0 + (it + 1) * P1_TROWS + (wid << 2) + lrow) * DD + lcol;
            const float* vp2 = Vb + (size_t)(n0 + (it + 1) * P1_TROWS + (wid << 2) + lrow) * DD + lcol;
            k0 = *(const float4*)kp2;
            k1 = *(const float4*)(kp2 + 4);
            v0 = *(const float4*)vp2;
            v1 = *(const float4*)(vp2 + 4);
        }

        // accumulate: warp w handles rows {w, w+8, w+16, w+24}
#pragma unroll
        for (int rr = 0; rr < 4; ++rr) {
            const int r = wid + (rr << 3);
            const float* kr = kn + r * KST + (ti << 3);
            const float* vr = vv + r * KST + (tj << 4);
            float4 ka  = ((const float4*)kr)[0];
            float4 kb4 = ((const float4*)kr)[1];
            float4 va  = ((const float4*)vr)[0];
            float4 vb4 = ((const float4*)vr)[1];
            float4 vc  = ((const float4*)vr)[2];
            float4 vd4 = ((const float4*)vr)[3];
            float kk[8] = {ka.x, ka.y, ka.z, ka.w, kb4.x, kb4.y, kb4.z, kb4.w};
            float2 vv2[8] = {
                make_float2(va.x, va.y),  make_float2(va.z, va.w),
                make_float2(vb4.x, vb4.y), make_float2(vb4.z, vb4.w),
                make_float2(vc.x, vc.y),  make_float2(vc.z, vc.w),
                make_float2(vd4.x, vd4.y), make_float2(vd4.z, vd4.w)};
#pragma unroll
            for (int i = 0; i < 8; i++) {
                float2 kd2 = make_float2(kk[i], kk[i]);
#pragma unroll
                for (int j = 0; j < 8; j++)
                    acc[i][j] = ffma2(kd2, vv2[j], acc[i][j]);
            }
        }
        __syncthreads();
    }

    // stage warp partials to smem
    float* st = stage + wid * (DD * SST);
#pragma unroll
    for (int i = 0; i < 8; i++) {
        const int d = (ti << 3) + i;
#pragma unroll
        for (int j = 0; j < 8; j++) {
            const int e = (tj << 4) + (j << 1);
            *(float2*)(st + d * SST + e) = acc[i][j];
        }
    }
    __syncthreads();

    // reduce 8 partials -> atomicAdd into g_ctx
    const int d  = tid >> 2;
    const int e0 = (tid & 3) << 4;
    float4 r0 = make_float4(0, 0, 0, 0), r1 = r0, r2 = r0, r3 = r0;
#pragma unroll
    for (int w = 0; w < 8; w++) {
        const float4* p = (const float4*)(stage + (w * DD + d) * SST + e0);
        float4 a0 = p[0], a1 = p[1], a2 = p[2], a3 = p[3];
        r0.x += a0.x; r0.y += a0.y; r0.z += a0.z; r0.w += a0.w;
        r1.x += a1.x; r1.y += a1.y; r1.z += a1.z; r1.w += a1.w;
        r2.x += a2.x; r2.y += a2.y; r2.z += a2.z; r2.w += a2.w;
        r3.x += a3.x; r3.y += a3.y; r3.z += a3.z; r3.w += a3.w;
    }
    float* dst = g_ctx + b * DD * DD + d * DD + e0;
    atomicAdd(dst + 0,  r0.x); atomicAdd(dst + 1,  r0.y);
    atomicAdd(dst + 2,  r0.z); atomicAdd(dst + 3,  r0.w);
    atomicAdd(dst + 4,  r1.x); atomicAdd(dst + 5,  r1.y);
    atomicAdd(dst + 6,  r1.z); atomicAdd(dst + 7,  r1.w);
    atomicAdd(dst + 8,  r2.x); atomicAdd(dst + 9,  r2.y);
    atomicAdd(dst + 10, r2.z); atomicAdd(dst + 11, r2.w);
    atomicAdd(dst + 12, r3.x); atomicAdd(dst + 13, r3.y);
    atomicAdd(dst + 14, r3.z); atomicAdd(dst + 15, r3.w);
}

// ============================ PASS 2 ============================
// grid (P2_CHUNKS, BB), 256 threads. ctx in smem; q softmaxed in regs,
// stored transposed qt[d][row] so the d-loop is shuffle-free float4 reads.
__global__ void __launch_bounds__(256, 2) out_kernel(
    const float* __restrict__ Q, float* __restrict__ OUT)
{
    __shared__ float sctx[DD * DD];       // [d][e]
    __shared__ float qt[DD][QST];         // [d][row(64)+pad]

    const int b  = blockIdx.y;
    const int n0 = blockIdx.x * P2_CROWS;

    const int tid  = threadIdx.x;
    const int wid  = tid >> 5;
    const int lane = tid & 31;
    const int lrow = lane >> 3;
    const int lcol = (lane & 7) << 3;

    const float* Qb = Q + ((size_t)b * NN) * DD;
    float* Ob       = OUT + ((size_t)b * NN) * DD;

    {   // load ctx (visible after first __syncthreads below)
        const float4* src = (const float4*)(g_ctx + b * DD * DD);
        float4* dst = (float4*)sctx;
        for (int i = tid; i < (DD * DD) / 4; i += 256) dst[i] = src[i];
    }

    // prefetch tile 0: each warp loads 8 rows (two 4-row sub-batches)
    const float* qp0 = Qb + (size_t)(n0 + (wid << 3) + lrow) * DD + lcol;
    float4 qa0 = *(const float4*)qp0;
    float4 qb0 = *(const float4*)(qp0 + 4);
    float4 qa1 = *(const float4*)(qp0 + 4 * DD);
    float4 qb1 = *(const float4*)(qp0 + 4 * DD + 4);

    for (int it = 0; it < P2_NT; ++it) {
        __syncthreads();  // prev-iter FMA reads of qt done (no-op cost at it=0)

        float o[8];
        const int srow = (wid << 3) + lrow;
        softmax8(qa0, qb0, o);
#pragma unroll
        for (int i = 0; i < 8; i++) qt[lcol + i][srow] = o[i];
        softmax8(qa1, qb1, o);
#pragma unroll
        for (int i = 0; i < 8; i++) qt[lcol + i][srow + 4] = o[i];
        __syncthreads();

        // prefetch next tile (overlaps FMA phase)
        if (it + 1 < P2_NT) {
            const float* qp = Qb + (size_t)(n0 + (it + 1) * P2_TROWS + (wid << 3) + lrow) * DD + lcol;
            qa0 = *(const float4*)qp;
            qb0 = *(const float4*)(qp + 4);
            qa1 = *(const float4*)(qp + 4 * DD);
            qb1 = *(const float4*)(qp + 4 * DD + 4);
        }

        // warp 'wid' computes rows [8*wid, 8*wid+8) x all 64 e; lane owns e={2*lane,2*lane+1}
        float2 acc[4][2];
#pragma unroll
        for (int rp = 0; rp < 4; rp++) {
            acc[rp][0] = make_float2(0.f, 0.f);
            acc[rp][1] = make_float2(0.f, 0.f);
        }

        const float* qbase = &qt[0][wid << 3];
        const float* cbase = sctx + (lane << 1);
#pragma unroll 16
        for (int d = 0; d < DD; ++d) {
            float4 qA = *(const float4*)(qbase + d * QST);
            float4 qB = *(const float4*)(qbase + d * QST + 4);
            float2 c  = *(const float2*)(cbase + d * DD);
            float2 cx = make_float2(c.x, c.x);
            float2 cy = make_float2(c.y, c.y);
            float2 q01 = make_float2(qA.x, qA.y);
            float2 q23 = make_float2(qA.z, qA.w);
            float2 q45 = make_float2(qB.x, qB.y);
            float2 q67 = make_float2(qB.z, qB.w);
            acc[0][0] = ffma2(q01, cx, acc[0][0]);
            acc[0][1] = ffma2(q01, cy, acc[0][1]);
            acc[1][0] = ffma2(q23, cx, acc[1][0]);
            acc[1][1] = ffma2(q23, cy, acc[1][1]);
            acc[2][0] = ffma2(q45, cx, acc[2][0]);
            acc[2][1] = ffma2(q45, cy, acc[2][1]);
            acc[3][0] = ffma2(q67, cx, acc[3][0]);
            acc[3][1] = ffma2(q67, cy, acc[3][1]);
        }

        const int rowbase = n0 + it * P2_TROWS + (wid << 3);
#pragma unroll
        for (int rp = 0; rp < 4; ++rp) {
            float2 lo = make_float2(acc[rp][0].x, acc[rp][1].x);
            float2 hi = make_float2(acc[rp][0].y, acc[rp][1].y);
            *(float2*)(Ob + (size_t)(rowbase + (rp << 1)) * DD + (lane << 1))     = lo;
            *(float2*)(Ob + (size_t)(rowbase + (rp << 1) + 1) * DD + (lane << 1)) = hi;
        }
    }
}

// ============================ launch ============================
extern "C" void kernel_launch(void* const* d_in, const int* in_sizes, int n_in,
                              void* d_out, int out_size) {
    (void)in_sizes; (void)n_in; (void)out_size;
    const float* q = (const float*)d_in[0];
    const float* k = (const float*)d_in[1];
    const float* v = (const float*)d_in[2];
    float* out = (float*)d_out;

    const int P1_SMEM = (2 * P1_TROWS * KST + 8 * DD * SST) * (int)sizeof(float);
    cudaFuncSetAttribute(ctx_kernel, cudaFuncAttributeMaxDynamicSharedMemorySize, P1_SMEM);

    zero_ctx_kernel<<<(BB * DD * DD + 255) / 256, 256>>>();
    ctx_kernel<<<dim3(P1_CHUNKS, BB), 256, P1_SMEM>>>(k, v);
    out_kernel<<<dim3(P2_CHUNKS, BB), 256>>>(q, out);
}

// round 6
// speedup vs baseline: 1.5128x; 1.5128x over previous
#include <cuda_runtime.h>
#include <cuda_bf16.h>
#include <cstdint>

#define BB 32
#define NN 16384
#define DD 64
#define CH 16
#define RPC (NN / CH)   // 1024 rows per CTA
#define NT (RPC / 64)   // 16 tiles of 64 rows

__device__ float g_ctx[BB * DD * DD];

__device__ __forceinline__ uint32_t s2u(const void* p) {
    uint32_t a; asm("{.reg .u64 t; cvta.to.shared.u64 t, %1; cvt.u32.u64 %0, t;}" : "=r"(a) : "l"(p)); return a;
}
#define STS32(a,v)  asm volatile("st.shared.b32 [%0], %1;" :: "r"(a), "r"(v) : "memory")
#define STS16(a,v)  asm volatile("st.shared.b16 [%0], %1;" :: "r"(a), "h"(v) : "memory")
#define STS128(a,r0,r1,r2,r3) asm volatile("st.shared.v4.b32 [%0], {%1,%2,%3,%4};" :: "r"(a),"r"(r0),"r"(r1),"r"(r2),"r"(r3) : "memory")

__device__ __forceinline__ void ldsm4(uint32_t* r, uint32_t addr) {
    asm volatile("ldmatrix.sync.aligned.m8n8.x4.shared.b16 {%0,%1,%2,%3}, [%4];"
        : "=r"(r[0]), "=r"(r[1]), "=r"(r[2]), "=r"(r[3]) : "r"(addr));
}
__device__ __forceinline__ void mma16816(float* c, const uint32_t* a, const uint32_t* b) {
    asm volatile("mma.sync.aligned.m16n8k16.row.col.f32.bf16.bf16.f32 "
        "{%0,%1,%2,%3}, {%4,%5,%6,%7}, {%8,%9}, {%0,%1,%2,%3};"
        : "+f"(c[0]), "+f"(c[1]), "+f"(c[2]), "+f"(c[3])
        : "r"(a[0]), "r"(a[1]), "r"(a[2]), "r"(a[3]), "r"(b[0]), "r"(b[1]));
}
// x = hi + lo (bf16 each); pack a->low half, b->high half of each b32
__device__ __forceinline__ void split_pack(float a, float b, uint32_t& h, uint32_t& l) {
    asm("cvt.rn.bf16x2.f32 %0, %1, %2;" : "=r"(h) : "f"(b), "f"(a));
    float la = a - __uint_as_float(h << 16), lb = b - __uint_as_float(h & 0xffff0000u);
    asm("cvt.rn.bf16x2.f32 %0, %1, %2;" : "=r"(l) : "f"(lb), "f"(la));
}
// XOR-permute 8-array: x_new[j] = x_old[j ^ m]
__device__ __forceinline__ void xperm(float* x, int m) {
#pragma unroll
    for (int s = 1; s < 8; s <<= 1) {
        bool c = (m & s) != 0;
#pragma unroll
        for (int j = 0; j < 8; j++) if (!(j & s)) {
            float a = x[j], b = x[j | s];
            x[j] = c ? b : a; x[j | s] = c ? a : b;
        }
    }
}
__device__ __forceinline__ void ld2(const float* p, float* a, float* b) {
    float4 t0 = ((const float4*)p)[0], t1 = ((const float4*)p)[1];
    float4 t2 = ((const float4*)(p + DD))[0], t3 = ((const float4*)(p + DD))[1];
    a[0]=t0.x;a[1]=t0.y;a[2]=t0.z;a[3]=t0.w;a[4]=t1.x;a[5]=t1.y;a[6]=t1.z;a[7]=t1.w;
    b[0]=t2.x;b[1]=t2.y;b[2]=t2.z;b[3]=t2.w;b[4]=t3.x;b[5]=t3.y;b[6]=t3.z;b[7]=t3.w;
}
// smem tiles: 64 rows x 128B (64 bf16), 16B chunks XOR-swizzled: phys_chunk = c ^ (row&7)
// A fragment (m16k16) addresses: blocks (m0-7,k0-7),(m8-15,k0-7),(m0-7,k8-15),(m8-15,k8-15)
__device__ __forceinline__ uint32_t a_addr(uint32_t base, int m0, int kc, int lane) {
    int rr = m0 + (lane & 7) + (((lane >> 3) & 1) << 3);
    int cc = kc + (lane >> 4);
    return base + rr * 128 + ((cc ^ (rr & 7)) << 4);
}
// B x4 covering 16 n-rows: blocks (n0-7,kc),(n0-7,kc+1),(n8-15,kc),(n8-15,kc+1)
__device__ __forceinline__ uint32_t b_addr(uint32_t base, int n0, int kc, int lane) {
    int rr = n0 + (lane & 7) + ((lane >> 4) << 3);
    int cc = kc + ((lane >> 3) & 1);
    return base + rr * 128 + ((cc ^ (rr & 7)) << 4);
}

__global__ void zero_ctx_kernel() {
    int i = blockIdx.x * blockDim.x + threadIdx.x;
    if (i < BB * DD * DD) g_ctx[i] = 0.f;
}

// ===== pass 1: ctx[d][e] = sum_n softmax(k)[n][d] * v[n][e] =====
__global__ void __launch_bounds__(256) ctx_kernel(const float* __restrict__ K4, const float* __restrict__ V4) {
    __shared__ __align__(1024) char sm[32768];
    const uint32_t sA = s2u(sm), sB = sA + 16384;   // each: hi plane 8KB + lo plane 8KB
    const int tid = threadIdx.x, wid = tid >> 5, lane = tid & 31;
    const int dblk = lane >> 2, p = lane & 3, d0 = dblk << 3;
    const int nloc = (wid << 3) + (p << 1);
    const uint32_t cbase = (uint32_t)((wid << 4) | (p << 2));
    const int b = blockIdx.y;
    const long base = ((long)b * NN + (long)blockIdx.x * RPC) * DD;
    const int m0 = (wid & 3) << 4;   // d-slice
    const int e0 = (wid >> 2) << 5;  // e-slice

    float acc[4][4];
#pragma unroll
    for (int i = 0; i < 4; i++)
#pragma unroll
        for (int j = 0; j < 4; j++) acc[i][j] = 0.f;

    float ka[8], kb[8], va[8], vb[8];
    ld2(K4 + base + (long)nloc * DD + d0, ka, kb);
    ld2(V4 + base + (long)nloc * DD + d0, va, vb);

    for (int t = 0; t < NT; ++t) {
        // softmax over d for the two owned rows (8 lanes per row: xor 4,8,16)
        float mA = ka[0], mB = kb[0];
#pragma unroll
        for (int j = 1; j < 8; j++) { mA = fmaxf(mA, ka[j]); mB = fmaxf(mB, kb[j]); }
#pragma unroll
        for (int s = 4; s <= 16; s <<= 1) {
            mA = fmaxf(mA, __shfl_xor_sync(~0u, mA, s));
            mB = fmaxf(mB, __shfl_xor_sync(~0u, mB, s));
        }
        float sa = 0.f, sb = 0.f;
#pragma unroll
        for (int j = 0; j < 8; j++) {
            ka[j] = __expf(ka[j] - mA); sa += ka[j];
            kb[j] = __expf(kb[j] - mB); sb += kb[j];
        }
#pragma unroll
        for (int s = 4; s <= 16; s <<= 1) {
            sa += __shfl_xor_sync(~0u, sa, s);
            sb += __shfl_xor_sync(~0u, sb, s);
        }
        float ia = __frcp_rn(sa), ib = __frcp_rn(sb);
#pragma unroll
        for (int j = 0; j < 8; j++) { ka[j] *= ia; kb[j] *= ib; }
        xperm(ka, dblk); xperm(kb, dblk); xperm(va, dblk); xperm(vb, dblk);
        // conflict-free transposed stores: A=k^T [d][n], B=v^T [e][n]
#pragma unroll
        for (int j = 0; j < 8; j++) {
            const int dd = d0 + (j ^ dblk);
            const uint32_t col = cbase ^ (uint32_t)((dd & 7) << 4);
            uint32_t h, l;
            split_pack(ka[j], kb[j], h, l);
            STS32(sA + dd * 128 + col, h); STS32(sA + 8192 + dd * 128 + col, l);
            split_pack(va[j], vb[j], h, l);
            STS32(sB + dd * 128 + col, h); STS32(sB + 8192 + dd * 128 + col, l);
        }
        __syncthreads();
        if (t + 1 < NT) {
            ld2(K4 + base + (long)((t + 1) * 64 + nloc) * DD + d0, ka, kb);
            ld2(V4 + base + (long)((t + 1) * 64 + nloc) * DD + d0, va, vb);
        }
#pragma unroll
        for (int ks = 0; ks < 4; ++ks) {
            uint32_t ah[4], al[4], bh[8], bl[8];
            ldsm4(ah, a_addr(sA, m0, 2 * ks, lane));
            ldsm4(al, a_addr(sA + 8192, m0, 2 * ks, lane));
            ldsm4(bh,     b_addr(sB, e0, 2 * ks, lane));
            ldsm4(bh + 4, b_addr(sB, e0 + 16, 2 * ks, lane));
            ldsm4(bl,     b_addr(sB + 8192, e0, 2 * ks, lane));
            ldsm4(bl + 4, b_addr(sB + 8192, e0 + 16, 2 * ks, lane));
#pragma unroll
            for (int nt2 = 0; nt2 < 4; ++nt2) {
                mma16816(acc[nt2], ah, &bh[2 * nt2]);
                mma16816(acc[nt2], al, &bh[2 * nt2]);
                mma16816(acc[nt2], ah, &bl[2 * nt2]);
            }
        }
        __syncthreads();
    }
    // epilogue: c-frag (row=t/4 [+8], col=2(t%4)[+1]) -> atomicAdd
    const int row = lane >> 2, colp = (lane & 3) << 1;
    float* g = g_ctx + b * 4096;
#pragma unroll
    for (int nt2 = 0; nt2 < 4; ++nt2) {
        const int e = e0 + 8 * nt2 + colp;
        atomicAdd(g + (m0 + row) * 64 + e,     acc[nt2][0]);
        atomicAdd(g + (m0 + row) * 64 + e + 1, acc[nt2][1]);
        atomicAdd(g + (m0 + row + 8) * 64 + e,     acc[nt2][2]);
        atomicAdd(g + (m0 + row + 8) * 64 + e + 1, acc[nt2][3]);
    }
}

// ===== pass 2: out[n][e] = sum_d softmax(q)[n][d] * ctx[d][e] =====
__global__ void __launch_bounds__(256) out_kernel(const float* __restrict__ Q4, float* __restrict__ OUT) {
    __shared__ __align__(1024) char sm[49152];
    const uint32_t sA = s2u(sm), sB = sA + 16384;
    float* stg = (float*)(sm + 32768);   // 64x64 f32 staging
    const int tid = threadIdx.x, wid = tid >> 5, lane = tid & 31;
    const int b = blockIdx.y;
    const long base = ((long)b * NN + (long)blockIdx.x * RPC) * DD;
    const int nrow = tid >> 2, sub = tid & 3;
    const int m0 = (wid & 3) << 4;   // n-slice
    const int e0 = (wid >> 2) << 5;  // e-slice

    {   // B = ctx^T [e][d] hi/lo, built once
        const float* gc = g_ctx + b * 4096;
        for (int i = tid; i < 4096; i += 256) {
            const int d = i >> 6, e = i & 63;
            uint32_t h, l; split_pack(gc[i], 0.f, h, l);
            const uint32_t ad = sB + e * 128 + ((((d >> 3) ^ (e & 7))) << 4) + ((d & 7) << 1);
            STS16(ad, (unsigned short)(h & 0xffff));
            STS16(ad + 8192, (unsigned short)(l & 0xffff));
        }
    }
    float f[16];
    {   const float* qp = Q4 + base + (long)nrow * DD + (sub << 4);
#pragma unroll
        for (int i = 0; i < 4; i++) { float4 x = ((const float4*)qp)[i]; f[4*i]=x.x; f[4*i+1]=x.y; f[4*i+2]=x.z; f[4*i+3]=x.w; }
    }
    for (int t = 0; t < NT; ++t) {
        // softmax over d (row shared by 4 lanes: xor 1,2)
        float m = f[0];
#pragma unroll
        for (int j = 1; j < 16; j++) m = fmaxf(m, f[j]);
        m = fmaxf(m, __shfl_xor_sync(~0u, m, 1));
        m = fmaxf(m, __shfl_xor_sync(~0u, m, 2));
        float s = 0.f;
#pragma unroll
        for (int j = 0; j < 16; j++) { f[j] = __expf(f[j] - m); s += f[j]; }
        s += __shfl_xor_sync(~0u, s, 1);
        s += __shfl_xor_sync(~0u, s, 2);
        float inv = __frcp_rn(s);
#pragma unroll
        for (int j = 0; j < 16; j++) f[j] *= inv;
        uint32_t h[8], l[8];
#pragma unroll
        for (int i = 0; i < 8; i++) split_pack(f[2 * i], f[2 * i + 1], h[i], l[i]);
        // A rows natural K-major: row nrow, chunks 2*sub, 2*sub+1
        const uint32_t rb = sA + nrow * 128;
        const uint32_t sw = (uint32_t)(nrow & 7);
        const uint32_t a0 = rb + (((2 * sub) ^ sw) << 4);
        const uint32_t a1 = rb + (((2 * sub + 1) ^ sw) << 4);
        STS128(a0, h[0], h[1], h[2], h[3]);
        STS128(a1, h[4], h[5], h[6], h[7]);
        STS128(a0 + 8192, l[0], l[1], l[2], l[3]);
        STS128(a1 + 8192, l[4], l[5], l[6], l[7]);
        __syncthreads();
        if (t + 1 < NT) {
            const float* qp = Q4 + base + (long)((t + 1) * 64 + nrow) * DD + (sub << 4);
#pragma unroll
            for (int i = 0; i < 4; i++) { float4 x = ((const float4*)qp)[i]; f[4*i]=x.x; f[4*i+1]=x.y; f[4*i+2]=x.z; f[4*i+3]=x.w; }
        }
        float acc[4][4];
#pragma unroll
        for (int i = 0; i < 4; i++)
#pragma unroll
            for (int j = 0; j < 4; j++) acc[i][j] = 0.f;
#pragma unroll
        for (int ks = 0; ks < 4; ++ks) {
            uint32_t ah[4], al[4], bh[8], bl[8];
            ldsm4(ah, a_addr(sA, m0, 2 * ks, lane));
            ldsm4(al, a_addr(sA + 8192, m0, 2 * ks, lane));
            ldsm4(bh,     b_addr(sB, e0, 2 * ks, lane));
            ldsm4(bh + 4, b_addr(sB, e0 + 16, 2 * ks, lane));
            ldsm4(bl,     b_addr(sB + 8192, e0, 2 * ks, lane));
            ldsm4(bl + 4, b_addr(sB + 8192, e0 + 16, 2 * ks, lane));
#pragma unroll
            for (int nt2 = 0; nt2 < 4; ++nt2) {
                mma16816(acc[nt2], ah, &bh[2 * nt2]);
                mma16816(acc[nt2], al, &bh[2 * nt2]);
                mma16816(acc[nt2], ah, &bl[2 * nt2]);
            }
        }
        // stage result tile
        const int row = lane >> 2, colp = (lane & 3) << 1;
#pragma unroll
        for (int nt2 = 0; nt2 < 4; ++nt2) {
            const int e = e0 + 8 * nt2 + colp;
            *(float2*)(stg + (m0 + row) * 64 + e)     = make_float2(acc[nt2][0], acc[nt2][1]);
            *(float2*)(stg + (m0 + row + 8) * 64 + e) = make_float2(acc[nt2][2], acc[nt2][3]);
        }
        __syncthreads();
        // coalesced output
        {
            const int rr = tid >> 2, cc = (tid & 3) << 4;
            float4* dst = (float4*)(OUT + base + (long)(t * 64 + rr) * DD + cc);
            const float4* s4 = (const float4*)(stg + rr * 64 + cc);
            dst[0] = s4[0]; dst[1] = s4[1]; dst[2] = s4[2]; dst[3] = s4[3];
        }
    }
}

extern "C" void kernel_launch(void* const* d_in, const int* in_sizes, int n_in,
                              void* d_out, int out_size) {
    (void)in_sizes; (void)n_in; (void)out_size;
    const float* q = (const float*)d_in[0];
    const float* k = (const float*)d_in[1];
    const float* v = (const float*)d_in[2];
    zero_ctx_kernel<<<(BB * DD * DD + 255) / 256, 256>>>();
    ctx_kernel<<<dim3(CH, BB), 256>>>(k, v);
    out_kernel<<<dim3(CH, BB), 256>>>(q, (float*)d_out);
}

// round 7
// speedup vs baseline: 1.9408x; 1.2829x over previous
#include <cuda_runtime.h>
#include <cuda_bf16.h>
#include <cstdint>

#define BB 32
#define NN 16384
#define DD 64
#define CH 32
#define RPC (NN / CH)   // 512 rows per CTA
#define NT (RPC / 64)   // 8 tiles of 64 rows

__device__ float g_ctx[BB * DD * DD];

__device__ __forceinline__ uint32_t s2u(const void* p) {
    uint32_t a; asm("{.reg .u64 t; cvta.to.shared.u64 t, %1; cvt.u32.u64 %0, t;}" : "=r"(a) : "l"(p)); return a;
}
#define STS32(a,v)  asm volatile("st.shared.b32 [%0], %1;" :: "r"(a), "r"(v) : "memory")
#define STS16(a,v)  asm volatile("st.shared.b16 [%0], %1;" :: "r"(a), "h"(v) : "memory")
#define STS128(a,r0,r1,r2,r3) asm volatile("st.shared.v4.b32 [%0], {%1,%2,%3,%4};" :: "r"(a),"r"(r0),"r"(r1),"r"(r2),"r"(r3) : "memory")

__device__ __forceinline__ void ldsm4(uint32_t* r, uint32_t addr) {
    asm volatile("ldmatrix.sync.aligned.m8n8.x4.shared.b16 {%0,%1,%2,%3}, [%4];"
        : "=r"(r[0]), "=r"(r[1]), "=r"(r[2]), "=r"(r[3]) : "r"(addr));
}
__device__ __forceinline__ void mma16816(float* c, const uint32_t* a, const uint32_t* b) {
    asm volatile("mma.sync.aligned.m16n8k16.row.col.f32.bf16.bf16.f32 "
        "{%0,%1,%2,%3}, {%4,%5,%6,%7}, {%8,%9}, {%0,%1,%2,%3};"
        : "+f"(c[0]), "+f"(c[1]), "+f"(c[2]), "+f"(c[3])
        : "r"(a[0]), "r"(a[1]), "r"(a[2]), "r"(a[3]), "r"(b[0]), "r"(b[1]));
}
__device__ __forceinline__ void split_pack(float a, float b, uint32_t& h, uint32_t& l) {
    asm("cvt.rn.bf16x2.f32 %0, %1, %2;" : "=r"(h) : "f"(b), "f"(a));
    float la = a - __uint_as_float(h << 16), lb = b - __uint_as_float(h & 0xffff0000u);
    asm("cvt.rn.bf16x2.f32 %0, %1, %2;" : "=r"(l) : "f"(lb), "f"(la));
}
__device__ __forceinline__ void xperm(float* x, int m) {
#pragma unroll
    for (int s = 1; s < 8; s <<= 1) {
        bool c = (m & s) != 0;
#pragma unroll
        for (int j = 0; j < 8; j++) if (!(j & s)) {
            float a = x[j], b = x[j | s];
            x[j] = c ? b : a; x[j | s] = c ? a : b;
        }
    }
}
__device__ __forceinline__ void ld2(const float* p, float* a, float* b) {
    float4 t0 = ((const float4*)p)[0], t1 = ((const float4*)p)[1];
    float4 t2 = ((const float4*)(p + DD))[0], t3 = ((const float4*)(p + DD))[1];
    a[0]=t0.x;a[1]=t0.y;a[2]=t0.z;a[3]=t0.w;a[4]=t1.x;a[5]=t1.y;a[6]=t1.z;a[7]=t1.w;
    b[0]=t2.x;b[1]=t2.y;b[2]=t2.z;b[3]=t2.w;b[4]=t3.x;b[5]=t3.y;b[6]=t3.z;b[7]=t3.w;
}
// tiles: 64 rows x 128B (64 bf16), 16B chunks XOR-swizzled: phys_chunk = c ^ (row&7)
__device__ __forceinline__ uint32_t a_addr(uint32_t base, int m0, int kc, int lane) {
    int rr = m0 + (lane & 7) + (((lane >> 3) & 1) << 3);
    int cc = kc + (lane >> 4);
    return base + rr * 128 + ((cc ^ (rr & 7)) << 4);
}
__device__ __forceinline__ uint32_t b_addr(uint32_t base, int n0, int kc, int lane) {
    int rr = n0 + (lane & 7) + ((lane >> 4) << 3);
    int cc = kc + ((lane >> 3) & 1);
    return base + rr * 128 + ((cc ^ (rr & 7)) << 4);
}

__global__ void zero_ctx_kernel() {
    int i = blockIdx.x * blockDim.x + threadIdx.x;
    if (i < BB * DD * DD) g_ctx[i] = 0.f;
}

// ===== pass 1: ctx[d][e] = sum_n softmax(k)[n][d] * v[n][e] =====
// dbuf smem (2x32KB dynamic). warp grid: 2(m) x 2(e) x 2(k-group), partials merged by atomics.
__global__ void __launch_bounds__(256, 2) ctx_kernel(const float* __restrict__ K4, const float* __restrict__ V4) {
    extern __shared__ __align__(1024) char smd[];
    const uint32_t sAll = s2u(smd);
    const int tid = threadIdx.x, wid = tid >> 5, lane = tid & 31;
    const int dblk = lane >> 2, p = lane & 3, d0 = dblk << 3;
    const int nloc = (wid << 3) + (p << 1);
    const uint32_t cbase = (uint32_t)((wid << 4) | (p << 2));
    const int b = blockIdx.y;
    const long base = ((long)b * NN + (long)blockIdx.x * RPC) * DD;
    const int kg = wid & 1, m0 = ((wid >> 1) & 1) << 5, e0 = ((wid >> 2) & 1) << 5;

    float acc[2][4][4];
#pragma unroll
    for (int i = 0; i < 2; i++)
#pragma unroll
        for (int j = 0; j < 4; j++)
#pragma unroll
            for (int r = 0; r < 4; r++) acc[i][j][r] = 0.f;

    float ka[8], kb[8], va[8], vb[8];
    ld2(K4 + base + (long)nloc * DD + d0, ka, kb);
    ld2(V4 + base + (long)nloc * DD + d0, va, vb);

    for (int t = 0; t < NT; ++t) {
        // softmax over d for two owned rows (8 lanes/row: xor 4,8,16)
        float mA = ka[0], mB = kb[0];
#pragma unroll
        for (int j = 1; j < 8; j++) { mA = fmaxf(mA, ka[j]); mB = fmaxf(mB, kb[j]); }
#pragma unroll
        for (int s = 4; s <= 16; s <<= 1) {
            mA = fmaxf(mA, __shfl_xor_sync(~0u, mA, s));
            mB = fmaxf(mB, __shfl_xor_sync(~0u, mB, s));
        }
        float sa = 0.f, sb = 0.f;
#pragma unroll
        for (int j = 0; j < 8; j++) {
            ka[j] = __expf(ka[j] - mA); sa += ka[j];
            kb[j] = __expf(kb[j] - mB); sb += kb[j];
        }
#pragma unroll
        for (int s = 4; s <= 16; s <<= 1) {
            sa += __shfl_xor_sync(~0u, sa, s);
            sb += __shfl_xor_sync(~0u, sb, s);
        }
        float ia = __frcp_rn(sa), ib = __frcp_rn(sb);
#pragma unroll
        for (int j = 0; j < 8; j++) { ka[j] *= ia; kb[j] *= ib; }
        xperm(ka, dblk); xperm(kb, dblk); xperm(va, dblk); xperm(vb, dblk);

        const uint32_t buf = sAll + (uint32_t)((t & 1) << 15);
#pragma unroll
        for (int j = 0; j < 8; j++) {
            const int dd = d0 + (j ^ dblk);
            const uint32_t col = cbase ^ (uint32_t)((dd & 7) << 4);
            uint32_t h, l;
            split_pack(ka[j], kb[j], h, l);
            STS32(buf + dd * 128 + col, h); STS32(buf + 8192 + dd * 128 + col, l);
            split_pack(va[j], vb[j], h, l);
            STS32(buf + 16384 + dd * 128 + col, h); STS32(buf + 24576 + dd * 128 + col, l);
        }
        __syncthreads();   // STS(t) done AND all warps' MMA(t-1) done (other buffer safe)
        if (t + 1 < NT) {
            ld2(K4 + base + (long)((t + 1) * 64 + nloc) * DD + d0, ka, kb);
            ld2(V4 + base + (long)((t + 1) * 64 + nloc) * DD + d0, va, vb);
        }
#pragma unroll
        for (int s = 0; s < 2; ++s) {
            const int kc = ((kg << 1) + s) << 1;
            uint32_t ah[8], al[8], bx[8];
            ldsm4(ah,     a_addr(buf,        m0,      kc, lane));
            ldsm4(ah + 4, a_addr(buf,        m0 + 16, kc, lane));
            ldsm4(al,     a_addr(buf + 8192, m0,      kc, lane));
            ldsm4(al + 4, a_addr(buf + 8192, m0 + 16, kc, lane));
            ldsm4(bx,     b_addr(buf + 16384, e0,      kc, lane));
            ldsm4(bx + 4, b_addr(buf + 16384, e0 + 16, kc, lane));
#pragma unroll
            for (int mf = 0; mf < 2; ++mf)
#pragma unroll
                for (int nf = 0; nf < 4; ++nf) {
                    mma16816(acc[mf][nf], ah + 4 * mf, &bx[2 * nf]);
                    mma16816(acc[mf][nf], al + 4 * mf, &bx[2 * nf]);
                }
            ldsm4(bx,     b_addr(buf + 24576, e0,      kc, lane));
            ldsm4(bx + 4, b_addr(buf + 24576, e0 + 16, kc, lane));
#pragma unroll
            for (int mf = 0; mf < 2; ++mf)
#pragma unroll
                for (int nf = 0; nf < 4; ++nf)
                    mma16816(acc[mf][nf], ah + 4 * mf, &bx[2 * nf]);
        }
    }
    // epilogue: vector atomics into g_ctx
    const int row = lane >> 2, colp = (lane & 3) << 1;
    float* g = g_ctx + b * 4096;
#pragma unroll
    for (int mf = 0; mf < 2; ++mf)
#pragma unroll
        for (int nf = 0; nf < 4; ++nf) {
            const int rr = m0 + (mf << 4) + row;
            const int e = e0 + (nf << 3) + colp;
            atomicAdd((float2*)(g + rr * 64 + e),       make_float2(acc[mf][nf][0], acc[mf][nf][1]));
            atomicAdd((float2*)(g + (rr + 8) * 64 + e), make_float2(acc[mf][nf][2], acc[mf][nf][3]));
        }
}

// ===== pass 2: out[n][e] = sum_d softmax(q)[n][d] * ctx[d][e] =====
// A dbuf 2x16KB + B 16KB (static 48KB). B-frags hoisted to registers; direct frag STG.
__global__ void __launch_bounds__(256, 2) out_kernel(const float* __restrict__ Q4, float* __restrict__ OUT) {
    __shared__ __align__(1024) char sm[49152];
    const uint32_t sA = s2u(sm), sB = sA + 32768;
    const int tid = threadIdx.x, wid = tid >> 5, lane = tid & 31;
    const int b = blockIdx.y;
    const long base = ((long)b * NN + (long)blockIdx.x * RPC) * DD;
    const int nrow = tid >> 2, sub = tid & 3;
    const int m0 = (wid & 1) << 5, e0 = (wid >> 1) << 4;

    {   // B = ctx^T [e][d] hi/lo, built once
        const float* gc = g_ctx + b * 4096;
        for (int i = tid; i < 4096; i += 256) {
            const int d = i >> 6, e = i & 63;
            uint32_t h, l; split_pack(gc[i], 0.f, h, l);
            const uint32_t ad = sB + e * 128 + ((((d >> 3) ^ (e & 7))) << 4) + ((d & 7) << 1);
            STS16(ad, (unsigned short)(h & 0xffff));
            STS16(ad + 8192, (unsigned short)(l & 0xffff));
        }
    }
    __syncthreads();
    uint32_t bh[4][4], bl[4][4];   // hoisted B fragments (e16 per warp)
#pragma unroll
    for (int ks = 0; ks < 4; ++ks) {
        ldsm4(bh[ks], b_addr(sB, e0, 2 * ks, lane));
        ldsm4(bl[ks], b_addr(sB + 8192, e0, 2 * ks, lane));
    }

    float f[16];
    {   const float* qp = Q4 + base + (long)nrow * DD + (sub << 4);
#pragma unroll
        for (int i = 0; i < 4; i++) { float4 x = ((const float4*)qp)[i]; f[4*i]=x.x; f[4*i+1]=x.y; f[4*i+2]=x.z; f[4*i+3]=x.w; }
    }
    for (int t = 0; t < NT; ++t) {
        float m = f[0];
#pragma unroll
        for (int j = 1; j < 16; j++) m = fmaxf(m, f[j]);
        m = fmaxf(m, __shfl_xor_sync(~0u, m, 1));
        m = fmaxf(m, __shfl_xor_sync(~0u, m, 2));
        float s = 0.f;
#pragma unroll
        for (int j = 0; j < 16; j++) { f[j] = __expf(f[j] - m); s += f[j]; }
        s += __shfl_xor_sync(~0u, s, 1);
        s += __shfl_xor_sync(~0u, s, 2);
        float inv = __frcp_rn(s);
#pragma unroll
        for (int j = 0; j < 16; j++) f[j] *= inv;
        uint32_t h[8], l[8];
#pragma unroll
        for (int i = 0; i < 8; i++) split_pack(f[2 * i], f[2 * i + 1], h[i], l[i]);
        const uint32_t buf = sA + (uint32_t)((t & 1) << 14);
        const uint32_t rb = buf + nrow * 128;
        const uint32_t sw = (uint32_t)(nrow & 7);
        const uint32_t a0 = rb + (((2 * sub) ^ sw) << 4);
        const uint32_t a1 = rb + (((2 * sub + 1) ^ sw) << 4);
        STS128(a0, h[0], h[1], h[2], h[3]);
        STS128(a1, h[4], h[5], h[6], h[7]);
        STS128(a0 + 8192, l[0], l[1], l[2], l[3]);
        STS128(a1 + 8192, l[4], l[5], l[6], l[7]);
        __syncthreads();   // single sync: STS(t) visible, prev-iter ldsm (other buffer) done
        if (t + 1 < NT) {
            const float* qp = Q4 + base + (long)((t + 1) * 64 + nrow) * DD + (sub << 4);
#pragma unroll
            for (int i = 0; i < 4; i++) { float4 x = ((const float4*)qp)[i]; f[4*i]=x.x; f[4*i+1]=x.y; f[4*i+2]=x.z; f[4*i+3]=x.w; }
        }
        float acc[2][2][4];
#pragma unroll
        for (int i = 0; i < 2; i++)
#pragma unroll
            for (int j = 0; j < 2; j++)
#pragma unroll
                for (int r = 0; r < 4; r++) acc[i][j][r] = 0.f;
#pragma unroll
        for (int ks = 0; ks < 4; ++ks) {
            uint32_t ah[8], al[8];
            ldsm4(ah,     a_addr(buf,        m0,      2 * ks, lane));
            ldsm4(ah + 4, a_addr(buf,        m0 + 16, 2 * ks, lane));
            ldsm4(al,     a_addr(buf + 8192, m0,      2 * ks, lane));
            ldsm4(al + 4, a_addr(buf + 8192, m0 + 16, 2 * ks, lane));
#pragma unroll
            for (int mf = 0; mf < 2; ++mf)
#pragma unroll
                for (int nf = 0; nf < 2; ++nf) {
                    mma16816(acc[mf][nf], ah + 4 * mf, &bh[ks][2 * nf]);
                    mma16816(acc[mf][nf], al + 4 * mf, &bh[ks][2 * nf]);
                    mma16816(acc[mf][nf], ah + 4 * mf, &bl[ks][2 * nf]);
                }
        }
        // direct fragment store (32B sectors, fully covered)
        const int row = lane >> 2, colp = (lane & 3) << 1;
#pragma unroll
        for (int mf = 0; mf < 2; ++mf)
#pragma unroll
            for (int nf = 0; nf < 2; ++nf) {
                const long rr = (long)(t * 64 + m0 + (mf << 4) + row);
                const int e = e0 + (nf << 3) + colp;
                *(float2*)(OUT + base + rr * 64 + e)       = make_float2(acc[mf][nf][0], acc[mf][nf][1]);
                *(float2*)(OUT + base + (rr + 8) * 64 + e) = make_float2(acc[mf][nf][2], acc[mf][nf][3]);
            }
    }
}

extern "C" void kernel_launch(void* const* d_in, const int* in_sizes, int n_in,
                              void* d_out, int out_size) {
    (void)in_sizes; (void)n_in; (void)out_size;
    const float* q = (const float*)d_in[0];
    const float* k = (const float*)d_in[1];
    const float* v = (const float*)d_in[2];
    cudaFuncSetAttribute(ctx_kernel, cudaFuncAttributeMaxDynamicSharedMemorySize, 65536);
    zero_ctx_kernel<<<(BB * DD * DD + 255) / 256, 256>>>();
    ctx_kernel<<<dim3(CH, BB), 256, 65536>>>(k, v);
    out_kernel<<<dim3(CH, BB), 256>>>(q, (float*)d_out);
}